// round 2
// baseline (speedup 1.0000x reference)
#include <cuda_runtime.h>
#include <cuda_bf16.h>
#include <cstdint>

// ============================================================
// Problem constants
// ============================================================
constexpr int N_ROWS = 4096;
constexpr int D_DIM  = 768;
constexpr float INV_T = 20.0f;   // 1 / 0.05

constexpr int BM = 128;          // anchor rows per CTA
constexpr int BN = 256;          // positive rows per CTA
constexpr int BK = 64;           // K chunk (64 bf16 = 128B row)
constexpr int MT = N_ROWS / BM;  // 32
constexpr int NT = N_ROWS / BN;  // 16
constexpr int NKC = D_DIM / BK;  // 12
constexpr int THREADS = 512;     // 16 warps: 4 (M) x 4 (N)
constexpr int STAGES = 3;

constexpr int A_BYTES = BM * 128;              // 16384
constexpr int B_BYTES = BN * 128;              // 32768
constexpr int STAGE_BYTES = A_BYTES + B_BYTES; // 49152
constexpr int SMEM_TOTAL = STAGES * STAGE_BYTES; // 147456

// ============================================================
// Device scratch (static — no allocation)
// ============================================================
__device__ __nv_bfloat16 g_A[N_ROWS * D_DIM];
__device__ __nv_bfloat16 g_B[N_ROWS * D_DIM];
__device__ float g_partials[NT * N_ROWS];
__device__ float g_last[N_ROWS];

// ============================================================
// Helpers
// ============================================================
__device__ __forceinline__ uint32_t smem_to_u32(const void* smem_ptr) {
    uint32_t addr;
    asm("{ .reg .u64 tmp; cvta.to.shared.u64 tmp, %1; cvt.u32.u64 %0, tmp; }"
        : "=r"(addr) : "l"(smem_ptr));
    return addr;
}

__device__ __forceinline__ uint32_t sw128(uint32_t off) {
    return off ^ ((off >> 3) & 0x70);
}

__device__ __forceinline__ void cp_async16(uint32_t dst, const void* src) {
    asm volatile("cp.async.cg.shared.global [%0], [%1], 16;"
                 :: "r"(dst), "l"(src) : "memory");
}

__device__ __forceinline__ void cp_commit() {
    asm volatile("cp.async.commit_group;" ::: "memory");
}

__device__ __forceinline__ void cp_wait2() {
    asm volatile("cp.async.wait_group %0;" :: "n"(STAGES - 1) : "memory");
}

__device__ __forceinline__ void ldmatrix_x4(uint32_t* r, uint32_t addr) {
    asm volatile("ldmatrix.sync.aligned.m8n8.x4.shared.b16 {%0,%1,%2,%3}, [%4];"
                 : "=r"(r[0]), "=r"(r[1]), "=r"(r[2]), "=r"(r[3]) : "r"(addr));
}

__device__ __forceinline__ void mma16816(float* c, const uint32_t* a,
                                         const uint32_t* b) {
    asm volatile(
        "mma.sync.aligned.m16n8k16.row.col.f32.bf16.bf16.f32 "
        "{%0,%1,%2,%3}, {%4,%5,%6,%7}, {%8,%9}, {%0,%1,%2,%3};"
        : "+f"(c[0]), "+f"(c[1]), "+f"(c[2]), "+f"(c[3])
        : "r"(a[0]), "r"(a[1]), "r"(a[2]), "r"(a[3]), "r"(b[0]), "r"(b[1]));
}

// ============================================================
// Kernel 1: f32 -> bf16 conversion (vectorized x4)
// ============================================================
__global__ void convert_kernel(const float* __restrict__ anchors,
                               const float* __restrict__ positives) {
    int i = blockIdx.x * blockDim.x + threadIdx.x;  // index over float4
    constexpr int TOTAL4 = N_ROWS * D_DIM / 4;
    if (i < TOTAL4) {
        float4 a = reinterpret_cast<const float4*>(anchors)[i];
        float4 p = reinterpret_cast<const float4*>(positives)[i];
        __nv_bfloat162 a01 = __floats2bfloat162_rn(a.x, a.y);
        __nv_bfloat162 a23 = __floats2bfloat162_rn(a.z, a.w);
        __nv_bfloat162 p01 = __floats2bfloat162_rn(p.x, p.y);
        __nv_bfloat162 p23 = __floats2bfloat162_rn(p.z, p.w);
        reinterpret_cast<__nv_bfloat162*>(g_A)[2 * i + 0] = a01;
        reinterpret_cast<__nv_bfloat162*>(g_A)[2 * i + 1] = a23;
        reinterpret_cast<__nv_bfloat162*>(g_B)[2 * i + 0] = p01;
        reinterpret_cast<__nv_bfloat162*>(g_B)[2 * i + 1] = p23;
    }
}

// ============================================================
// Kernel 2: bf16 HMMA GEMM fused with row exp-sum epilogue
// CTA (nt, mt): logits tile rows [mt*128,+128) x cols [nt*256,+256)
// ============================================================
__device__ __forceinline__ void issue_loads(uint32_t sb, int mt, int nt,
                                            int c, int tid) {
    const uint32_t st = (uint32_t)(c % STAGES) * STAGE_BYTES;
    const int kk = c * BK;
    // A: 128 rows x 128B -> 1024 x 16B vectors, 2 per thread
    #pragma unroll
    for (int v = tid; v < BM * 8; v += THREADS) {
        int row = v >> 3, c16 = v & 7;
        const void* src = g_A + (size_t)(mt * BM + row) * D_DIM + kk + c16 * 8;
        cp_async16(sb + st + sw128((uint32_t)(row * 128 + c16 * 16)), src);
    }
    // B: 256 rows -> 2048 x 16B vectors, 4 per thread
    #pragma unroll
    for (int v = tid; v < BN * 8; v += THREADS) {
        int row = v >> 3, c16 = v & 7;
        const void* src = g_B + (size_t)(nt * BN + row) * D_DIM + kk + c16 * 8;
        cp_async16(sb + st + A_BYTES + sw128((uint32_t)(row * 128 + c16 * 16)),
                   src);
    }
}

__global__ void __launch_bounds__(THREADS, 1)
gemm_epilogue_kernel() {
    extern __shared__ char smem[];
    const int tid = threadIdx.x;
    const int lane = tid & 31;
    const int wid = tid >> 5;
    const int warpM = wid & 3;   // 0..3 -> 32-row band
    const int warpN = wid >> 2;  // 0..3 -> 64-col band
    const int nt = blockIdx.x;
    const int mt = blockIdx.y;
    const uint32_t sb = smem_to_u32(smem);

    float acc[16][4];  // [mi*8+ni][4]
    #pragma unroll
    for (int i = 0; i < 16; ++i)
        #pragma unroll
        for (int j = 0; j < 4; ++j) acc[i][j] = 0.0f;

    // Prologue: stages 0..STAGES-2
    issue_loads(sb, mt, nt, 0, tid);
    cp_commit();
    issue_loads(sb, mt, nt, 1, tid);
    cp_commit();

    // Precompute fragment smem offsets (stage-relative)
    // A: addr = row(lane&15) within 16-row tile, k-half = lane>>4
    const uint32_t a_row = (uint32_t)(warpM * 32 + (lane & 15));
    const uint32_t a_kb  = (uint32_t)((lane >> 4) * 16);
    // B: row = (lane&7) | ((lane>>4)<<3) within 16-row pair, k-half = (lane>>3)&1
    const uint32_t b_row = (uint32_t)(warpN * 64 + ((lane & 7) | ((lane >> 4) << 3)));
    const uint32_t b_kb  = (uint32_t)(((lane >> 3) & 1) * 16);

    for (int c = 0; c < NKC; ++c) {
        if (c + STAGES - 1 < NKC)
            issue_loads(sb, mt, nt, c + STAGES - 1, tid);
        cp_commit();
        cp_wait2();          // stage c resident
        __syncthreads();

        const uint32_t sA = sb + (uint32_t)(c % STAGES) * STAGE_BYTES;
        const uint32_t sB = sA + A_BYTES;

        #pragma unroll
        for (int ks = 0; ks < 4; ++ks) {
            uint32_t a[2][4];
            #pragma unroll
            for (int mi = 0; mi < 2; ++mi) {
                uint32_t off = (a_row + mi * 16) * 128 + ks * 32 + a_kb;
                ldmatrix_x4(a[mi], sA + sw128(off));
            }
            uint32_t b[4][4];
            #pragma unroll
            for (int np = 0; np < 4; ++np) {
                uint32_t off = (b_row + np * 16) * 128 + ks * 32 + b_kb;
                ldmatrix_x4(b[np], sB + sw128(off));
            }
            #pragma unroll
            for (int mi = 0; mi < 2; ++mi)
                #pragma unroll
                for (int ni = 0; ni < 8; ++ni)
                    mma16816(acc[mi * 8 + ni], a[mi], &b[ni >> 1][(ni & 1) * 2]);
        }
        __syncthreads();     // everyone done reading stage before overwrite
    }

    // ---- Fused epilogue: exp, diagonal, last-col, row reduction ----
    float* rowsum = reinterpret_cast<float*>(smem);  // reuse stage 0
    __syncthreads();
    if (tid < BM) rowsum[tid] = 0.0f;
    __syncthreads();

    #pragma unroll
    for (int mi = 0; mi < 2; ++mi) {
        #pragma unroll
        for (int h = 0; h < 2; ++h) {
            const int lr = warpM * 32 + mi * 16 + h * 8 + (lane >> 2);
            const int grow = mt * BM + lr;
            float rs = 0.0f;
            #pragma unroll
            for (int ni = 0; ni < 8; ++ni) {
                #pragma unroll
                for (int j = 0; j < 2; ++j) {
                    float v = acc[mi * 8 + ni][h * 2 + j] * INV_T;
                    int gcol = nt * BN + warpN * 64 + ni * 8 + (lane & 3) * 2 + j;
                    float e = __expf(v);
                    rs += e;
                    if (gcol == grow) rs += e;           // diagonal double-count
                    if (gcol == N_ROWS - 1) g_last[grow] = v;
                }
            }
            atomicAdd(&rowsum[lr], rs);
        }
    }
    __syncthreads();
    if (tid < BM)
        g_partials[nt * N_ROWS + mt * BM + tid] = rowsum[tid];
}

// ============================================================
// Kernel 3: deterministic finalize (single block)
// ============================================================
__global__ void __launch_bounds__(1024)
finalize_kernel(float* __restrict__ out) {
    __shared__ float red[1024];
    const int t = threadIdx.x;
    float acc = 0.0f;
    for (int r = t; r < N_ROWS; r += 1024) {
        float denom = 0.0f;
        #pragma unroll
        for (int n = 0; n < NT; ++n)
            denom += g_partials[n * N_ROWS + r];
        acc += logf(denom) - g_last[r];  // loss_r = log(denom) - logits[r,-1]
    }
    red[t] = acc;
    __syncthreads();
    #pragma unroll
    for (int s = 512; s > 0; s >>= 1) {
        if (t < s) red[t] += red[t + s];
        __syncthreads();
    }
    if (t == 0) out[0] = red[0];
}

// ============================================================
// Launch
// ============================================================
extern "C" void kernel_launch(void* const* d_in, const int* in_sizes, int n_in,
                              void* d_out, int out_size) {
    const float* anchors   = (const float*)d_in[0];
    const float* positives = (const float*)d_in[1];
    float* out = (float*)d_out;

    cudaFuncSetAttribute(gemm_epilogue_kernel,
                         cudaFuncAttributeMaxDynamicSharedMemorySize, SMEM_TOTAL);

    constexpr int TOTAL4 = N_ROWS * D_DIM / 4;
    convert_kernel<<<(TOTAL4 + 255) / 256, 256>>>(anchors, positives);

    dim3 grid(NT, MT);
    gemm_epilogue_kernel<<<grid, THREADS, SMEM_TOTAL>>>();

    finalize_kernel<<<1, 1024>>>(out);
}

// round 3
// speedup vs baseline: 1.1144x; 1.1144x over previous
#include <cuda_runtime.h>
#include <cuda.h>
#include <cuda_bf16.h>
#include <cstdint>

// ============================================================
// Problem constants
// ============================================================
constexpr int N_ROWS = 4096;
constexpr int D_DIM  = 768;
constexpr float INV_T = 20.0f;   // 1 / 0.05

constexpr int BM = 128;          // anchor rows per CTA
constexpr int BN = 256;          // positive rows per CTA
constexpr int BK = 64;           // K chunk (64 bf16 = 128B row)
constexpr int MT = N_ROWS / BM;  // 32
constexpr int NT = N_ROWS / BN;  // 16
constexpr int NKC = D_DIM / BK;  // 12
constexpr int THREADS = 512;     // 16 warps: 4 (M) x 4 (N)
constexpr int STAGES = 4;

constexpr int A_BYTES = BM * 128;              // 16384
constexpr int B_BYTES = BN * 128;              // 32768
constexpr int STAGE_BYTES = A_BYTES + B_BYTES; // 49152
constexpr int SMEM_TILES = STAGES * STAGE_BYTES; // 196608
constexpr int SMEM_TOTAL = 1024 + SMEM_TILES;    // barriers + tiles

// ============================================================
// Device scratch (static — no allocation)
// ============================================================
__device__ __nv_bfloat16 g_A[N_ROWS * D_DIM];
__device__ __nv_bfloat16 g_B[N_ROWS * D_DIM];
__device__ float g_partials[NT * N_ROWS];
__device__ float g_last[N_ROWS];

// ============================================================
// Helpers
// ============================================================
__device__ __forceinline__ uint32_t smem_to_u32(const void* smem_ptr) {
    uint32_t addr;
    asm("{ .reg .u64 tmp; cvta.to.shared.u64 tmp, %1; cvt.u32.u64 %0, tmp; }"
        : "=r"(addr) : "l"(smem_ptr));
    return addr;
}

__device__ __forceinline__ uint32_t sw128(uint32_t off) {
    return off ^ ((off >> 3) & 0x70);
}

__device__ __forceinline__ void ldmatrix_x4(uint32_t* r, uint32_t addr) {
    asm volatile("ldmatrix.sync.aligned.m8n8.x4.shared.b16 {%0,%1,%2,%3}, [%4];"
                 : "=r"(r[0]), "=r"(r[1]), "=r"(r[2]), "=r"(r[3]) : "r"(addr));
}

__device__ __forceinline__ void mma16816(float* c, const uint32_t* a,
                                         const uint32_t* b) {
    asm volatile(
        "mma.sync.aligned.m16n8k16.row.col.f32.bf16.bf16.f32 "
        "{%0,%1,%2,%3}, {%4,%5,%6,%7}, {%8,%9}, {%0,%1,%2,%3};"
        : "+f"(c[0]), "+f"(c[1]), "+f"(c[2]), "+f"(c[3])
        : "r"(a[0]), "r"(a[1]), "r"(a[2]), "r"(a[3]), "r"(b[0]), "r"(b[1]));
}

#define MBARRIER_INIT(mbar, count) \
    asm volatile("mbarrier.init.shared.b64 [%0], %1;" \
                 :: "r"((uint32_t)(mbar)), "r"((uint32_t)(count)) : "memory")

#define MBARRIER_EXPECT_TX(mbar, bytes) \
    asm volatile("mbarrier.arrive.expect_tx.shared.b64 _, [%0], %1;" \
                 :: "r"((uint32_t)(mbar)), "r"((uint32_t)(bytes)) : "memory")

#define MBARRIER_ARRIVE(mbar) \
    asm volatile("mbarrier.arrive.shared.b64 _, [%0];" \
                 :: "r"((uint32_t)(mbar)) : "memory")

#define MBARRIER_WAIT_PARITY(mbar, parity) do { \
    uint32_t _mbar = (uint32_t)(mbar); \
    uint32_t _parity = (uint32_t)(parity); \
    uint32_t _done; \
    asm volatile( \
        "{\n\t" \
        ".reg .pred p;\n\t" \
        "mbarrier.try_wait.parity.acquire.cta.shared::cta.b64 p, [%1], %2;\n\t" \
        "selp.b32 %0, 1, 0, p;\n\t" \
        "}" \
        : "=r"(_done) : "r"(_mbar), "r"(_parity) : "memory"); \
    if (!_done) { \
        asm volatile( \
            "{\n\t" \
            ".reg .pred P1;\n\t" \
            "WAIT_LOOP_%=:\n\t" \
            "mbarrier.try_wait.parity.acquire.cta.shared::cta.b64 P1, [%0], %1, 0x989680;\n\t" \
            "@P1 bra.uni WAIT_DONE_%=;\n\t" \
            "bra.uni WAIT_LOOP_%=;\n\t" \
            "WAIT_DONE_%=:\n\t" \
            "}" \
            :: "r"(_mbar), "r"(_parity) : "memory"); \
    } \
} while(0)

#define TMA_LOAD_2D(smem_addr, tmap_ptr, cx, cy, mbar) \
    asm volatile( \
        "cp.async.bulk.tensor.2d.shared::cta.global.tile.mbarrier::complete_tx::bytes " \
        "[%0], [%1, {%2, %3}], [%4];" \
        :: "r"((uint32_t)(smem_addr)), "l"(tmap_ptr), \
           "r"((int)(cx)), "r"((int)(cy)), "r"((uint32_t)(mbar)) \
        : "memory")

// ============================================================
// Kernel 1: f32 -> bf16 conversion (2x float4 per thread)
// ============================================================
__global__ void convert_kernel(const float* __restrict__ anchors,
                               const float* __restrict__ positives) {
    constexpr int HALF4 = N_ROWS * D_DIM / 8;  // float4 count per half
    int i = blockIdx.x * blockDim.x + threadIdx.x;
    #pragma unroll
    for (int h = 0; h < 2; ++h) {
        int idx = i + h * HALF4;
        float4 a = reinterpret_cast<const float4*>(anchors)[idx];
        float4 p = reinterpret_cast<const float4*>(positives)[idx];
        __nv_bfloat162 a01 = __floats2bfloat162_rn(a.x, a.y);
        __nv_bfloat162 a23 = __floats2bfloat162_rn(a.z, a.w);
        __nv_bfloat162 p01 = __floats2bfloat162_rn(p.x, p.y);
        __nv_bfloat162 p23 = __floats2bfloat162_rn(p.z, p.w);
        reinterpret_cast<__nv_bfloat162*>(g_A)[2 * idx + 0] = a01;
        reinterpret_cast<__nv_bfloat162*>(g_A)[2 * idx + 1] = a23;
        reinterpret_cast<__nv_bfloat162*>(g_B)[2 * idx + 0] = p01;
        reinterpret_cast<__nv_bfloat162*>(g_B)[2 * idx + 1] = p23;
    }
}

// ============================================================
// Kernel 2: TMA-fed bf16 HMMA GEMM fused with row exp-sum
// CTA (nt, mt): logits tile rows [mt*128,+128) x cols [nt*256,+256)
// SMEM: [0,32) full mbarriers, [64,96) empty mbarriers, tiles from 1024
// ============================================================
__global__ void __launch_bounds__(THREADS, 1)
gemm_epilogue_kernel(const __grid_constant__ CUtensorMap tmA,
                     const __grid_constant__ CUtensorMap tmB) {
    extern __shared__ char smem[];
    const int tid = threadIdx.x;
    const int lane = tid & 31;
    const int wid = tid >> 5;
    const int warpM = wid & 3;   // 0..3 -> 32-row band
    const int warpN = wid >> 2;  // 0..3 -> 64-col band
    const int nt = blockIdx.x;
    const int mt = blockIdx.y;
    const uint32_t sb = smem_to_u32(smem);

    auto full_bar  = [&](int s) { return sb + s * 8; };
    auto empty_bar = [&](int s) { return sb + 64 + s * 8; };
    auto stage_off = [&](int s) { return sb + 1024 + (uint32_t)s * STAGE_BYTES; };

    if (tid == 0) {
        #pragma unroll
        for (int s = 0; s < STAGES; ++s) {
            MBARRIER_INIT(full_bar(s), 1);
            MBARRIER_INIT(empty_bar(s), THREADS);
        }
        asm volatile("fence.proxy.async.shared::cta;" ::: "memory");
    }
    __syncthreads();

    // Prologue: fill all 4 stages
    if (tid == 0) {
        #pragma unroll
        for (int s = 0; s < STAGES; ++s) {
            MBARRIER_EXPECT_TX(full_bar(s), STAGE_BYTES);
            TMA_LOAD_2D(stage_off(s),           &tmA, s * BK, mt * BM, full_bar(s));
            TMA_LOAD_2D(stage_off(s) + A_BYTES, &tmB, s * BK, nt * BN, full_bar(s));
        }
    }

    float acc[16][4];
    #pragma unroll
    for (int i = 0; i < 16; ++i)
        #pragma unroll
        for (int j = 0; j < 4; ++j) acc[i][j] = 0.0f;

    // Fragment offsets (stage-relative)
    const uint32_t a_row = (uint32_t)(warpM * 32 + (lane & 15));
    const uint32_t a_kb  = (uint32_t)((lane >> 4) * 16);
    const uint32_t b_row = (uint32_t)(warpN * 64 + ((lane & 7) | ((lane >> 4) << 3)));
    const uint32_t b_kb  = (uint32_t)(((lane >> 3) & 1) * 16);

    for (int c = 0; c < NKC; ++c) {
        const int s = c & (STAGES - 1);
        const int ph = (c >> 2) & 1;
        MBARRIER_WAIT_PARITY(full_bar(s), ph);

        const uint32_t sA = stage_off(s);
        const uint32_t sB = sA + A_BYTES;

        #pragma unroll
        for (int ks = 0; ks < 4; ++ks) {
            uint32_t a[2][4];
            #pragma unroll
            for (int mi = 0; mi < 2; ++mi) {
                uint32_t off = (a_row + mi * 16) * 128 + ks * 32 + a_kb;
                ldmatrix_x4(a[mi], sA + sw128(off));
            }
            uint32_t b[4][4];
            #pragma unroll
            for (int np = 0; np < 4; ++np) {
                uint32_t off = (b_row + np * 16) * 128 + ks * 32 + b_kb;
                ldmatrix_x4(b[np], sB + sw128(off));
            }
            #pragma unroll
            for (int mi = 0; mi < 2; ++mi)
                #pragma unroll
                for (int ni = 0; ni < 8; ++ni)
                    mma16816(acc[mi * 8 + ni], a[mi], &b[ni >> 1][(ni & 1) * 2]);
        }

        MBARRIER_ARRIVE(empty_bar(s));

        // Producer: refill slot s with chunk c+4 once all warps drained it
        if (tid == 0 && c + STAGES < NKC) {
            MBARRIER_WAIT_PARITY(empty_bar(s), ph);
            MBARRIER_EXPECT_TX(full_bar(s), STAGE_BYTES);
            TMA_LOAD_2D(stage_off(s),           &tmA, (c + STAGES) * BK, mt * BM,
                        full_bar(s));
            TMA_LOAD_2D(stage_off(s) + A_BYTES, &tmB, (c + STAGES) * BK, nt * BN,
                        full_bar(s));
        }
    }

    // ---- Fused epilogue: exp, diagonal, last-col, row reduction ----
    __syncthreads();
    float* rowsum = reinterpret_cast<float*>(smem + 1024);  // reuse tile smem
    if (tid < BM) rowsum[tid] = 0.0f;
    __syncthreads();

    #pragma unroll
    for (int mi = 0; mi < 2; ++mi) {
        #pragma unroll
        for (int h = 0; h < 2; ++h) {
            const int lr = warpM * 32 + mi * 16 + h * 8 + (lane >> 2);
            const int grow = mt * BM + lr;
            float rs = 0.0f;
            #pragma unroll
            for (int ni = 0; ni < 8; ++ni) {
                #pragma unroll
                for (int j = 0; j < 2; ++j) {
                    float v = acc[mi * 8 + ni][h * 2 + j] * INV_T;
                    int gcol = nt * BN + warpN * 64 + ni * 8 + (lane & 3) * 2 + j;
                    float e = __expf(v);
                    rs += e;
                    if (gcol == grow) rs += e;           // diagonal double-count
                    if (gcol == N_ROWS - 1) g_last[grow] = v;
                }
            }
            atomicAdd(&rowsum[lr], rs);
        }
    }
    __syncthreads();
    if (tid < BM)
        g_partials[nt * N_ROWS + mt * BM + tid] = rowsum[tid];
}

// ============================================================
// Kernel 3: deterministic finalize (single block)
// ============================================================
__global__ void __launch_bounds__(1024)
finalize_kernel(float* __restrict__ out) {
    __shared__ float red[1024];
    const int t = threadIdx.x;
    float acc = 0.0f;
    for (int r = t; r < N_ROWS; r += 1024) {
        float denom = 0.0f;
        #pragma unroll
        for (int n = 0; n < NT; ++n)
            denom += g_partials[n * N_ROWS + r];
        acc += logf(denom) - g_last[r];  // loss_r = log(denom) - logits[r,-1]
    }
    red[t] = acc;
    __syncthreads();
    #pragma unroll
    for (int s = 512; s > 0; s >>= 1) {
        if (t < s) red[t] += red[t + s];
        __syncthreads();
    }
    if (t == 0) out[0] = red[0];
}

// ============================================================
// Launch
// ============================================================
typedef CUresult (*EncodeTiledFn)(
    CUtensorMap*, CUtensorMapDataType, cuuint32_t, void*,
    const cuuint64_t*, const cuuint64_t*, const cuuint32_t*, const cuuint32_t*,
    CUtensorMapInterleave, CUtensorMapSwizzle, CUtensorMapL2promotion,
    CUtensorMapFloatOOBfill);

extern "C" void kernel_launch(void* const* d_in, const int* in_sizes, int n_in,
                              void* d_out, int out_size) {
    const float* anchors   = (const float*)d_in[0];
    const float* positives = (const float*)d_in[1];
    float* out = (float*)d_out;

    // Resolve driver encode function through cudart (no -lcuda needed)
    void* fn = nullptr;
    cudaDriverEntryPointQueryResult qr;
    cudaGetDriverEntryPointByVersion("cuTensorMapEncodeTiled", &fn, 12000,
                                     cudaEnableDefault, &qr);
    EncodeTiledFn encode = (EncodeTiledFn)fn;

    void* pA = nullptr;
    void* pB = nullptr;
    cudaGetSymbolAddress(&pA, g_A);
    cudaGetSymbolAddress(&pB, g_B);

    CUtensorMap tmA, tmB;
    cuuint64_t dims[2]    = {(cuuint64_t)D_DIM, (cuuint64_t)N_ROWS};
    cuuint64_t strides[1] = {(cuuint64_t)D_DIM * sizeof(__nv_bfloat16)};
    cuuint32_t es[2]      = {1, 1};
    cuuint32_t boxA[2]    = {(cuuint32_t)BK, (cuuint32_t)BM};
    cuuint32_t boxB[2]    = {(cuuint32_t)BK, (cuuint32_t)BN};
    encode(&tmA, CU_TENSOR_MAP_DATA_TYPE_BFLOAT16, 2, pA, dims, strides, boxA,
           es, CU_TENSOR_MAP_INTERLEAVE_NONE, CU_TENSOR_MAP_SWIZZLE_128B,
           CU_TENSOR_MAP_L2_PROMOTION_L2_128B, CU_TENSOR_MAP_FLOAT_OOB_FILL_NONE);
    encode(&tmB, CU_TENSOR_MAP_DATA_TYPE_BFLOAT16, 2, pB, dims, strides, boxB,
           es, CU_TENSOR_MAP_INTERLEAVE_NONE, CU_TENSOR_MAP_SWIZZLE_128B,
           CU_TENSOR_MAP_L2_PROMOTION_L2_128B, CU_TENSOR_MAP_FLOAT_OOB_FILL_NONE);

    cudaFuncSetAttribute(gemm_epilogue_kernel,
                         cudaFuncAttributeMaxDynamicSharedMemorySize, SMEM_TOTAL);

    constexpr int HALF4 = N_ROWS * D_DIM / 8;
    convert_kernel<<<HALF4 / 256, 256>>>(anchors, positives);

    dim3 grid(NT, MT);
    gemm_epilogue_kernel<<<grid, THREADS, SMEM_TOTAL>>>(tmA, tmB);

    finalize_kernel<<<1, 1024>>>(out);
}